// round 16
// baseline (speedup 1.0000x reference)
#include <cuda_runtime.h>
#include <cuda_bf16.h>
#include <cstdint>
#include <cstddef>

// Problem constants
#define B_    32
#define C_    384
#define H_    32
#define W_    32
#define HW_   1024
#define HK_   16
#define WK_   16
#define HWK_  256
#define HEADS 6
#define DHEAD 64
#define INNER 384          // HEADS*DHEAD
#define SCALE 0.125f       // DIM_HEAD^-0.5
#define BN_EPS 1e-5f

typedef unsigned long long u64;

// ---------------------------------------------------------------------------
// tf32 helpers
// ---------------------------------------------------------------------------
__device__ __forceinline__ float to_tf32f(float x) {
    uint32_t r; asm("cvt.rna.tf32.f32 %0, %1;" : "=r"(r) : "f"(x));
    return __uint_as_float(r);
}
__device__ __forceinline__ void mma_tf32(float* d, const uint32_t* a, const uint32_t* b) {
    asm volatile(
        "mma.sync.aligned.m16n8k8.row.col.f32.tf32.tf32.f32 "
        "{%0,%1,%2,%3}, {%4,%5,%6,%7}, {%8,%9}, {%0,%1,%2,%3};"
        : "+f"(d[0]), "+f"(d[1]), "+f"(d[2]), "+f"(d[3])
        : "r"(a[0]), "r"(a[1]), "r"(a[2]), "r"(a[3]), "r"(b[0]), "r"(b[1]));
}
__device__ __forceinline__ void ldsm_x4(uint32_t* r, uint32_t addr) {
    asm volatile("ldmatrix.sync.aligned.m8n8.x4.shared.b16 {%0,%1,%2,%3}, [%4];"
        : "=r"(r[0]), "=r"(r[1]), "=r"(r[2]), "=r"(r[3]) : "r"(addr));
}
__device__ __forceinline__ void ldsm_x2(uint32_t* r, uint32_t addr) {
    asm volatile("ldmatrix.sync.aligned.m8n8.x2.shared.b16 {%0,%1}, [%2];"
        : "=r"(r[0]), "=r"(r[1]) : "r"(addr));
}
__device__ __forceinline__ void cp16(uint32_t dst, const void* src) {
    asm volatile("cp.async.ca.shared.global [%0], [%1], 16;" :: "r"(dst), "l"(src));
}

// ---------------------------------------------------------------------------
// Scratch (static device globals; no runtime allocation allowed)
// ---------------------------------------------------------------------------
__device__ float g_yq [(size_t)B_ * HW_ * C_];          // dw+bn out, Q path (tf32-rounded)
__device__ float g_ykv[(size_t)B_ * HWK_ * C_];         // dw+bn out, KV path (tf32-rounded)
__device__ float g_Q  [(size_t)B_ * HW_ * INNER];       // Q row-major (tf32-rounded)
__device__ float g_KV [(size_t)B_ * HWK_ * 2 * INNER];  // KV row-major (tf32-rounded)
__device__ float g_O  [(size_t)B_ * HW_ * INNER];       // attention out (tf32-rounded)

#define WQ_OFF  0
#define WKV_OFF (INNER * C_)                             // 147456
#define WO_OFF  (WQ_OFF + INNER * C_ + 2 * INNER * C_)   // 442368
__device__ float g_w[INNER * C_ + 2 * INNER * C_ + C_ * INNER];

// ---------------------------------------------------------------------------
// Kernel 0: pre-round weights to tf32 (rna)
// ---------------------------------------------------------------------------
__global__ __launch_bounds__(256)
void prep_weights(const float* __restrict__ q_pw, const float* __restrict__ kv_pw,
                  const float* __restrict__ out_w)
{
    int i = blockIdx.x * 256 + threadIdx.x;
    if (i < WKV_OFF)          g_w[i] = to_tf32f(q_pw[i]);
    else if (i < WO_OFF)      g_w[i] = to_tf32f(kv_pw[i - WKV_OFF]);
    else if (i < WO_OFF + C_ * INNER) g_w[i] = to_tf32f(out_w[i - WO_OFF]);
}

// ---------------------------------------------------------------------------
// Kernel 1: fused depthwise 3x3 (+BN), 8-channel groups, transposed tf32 out
// ---------------------------------------------------------------------------
__global__ __launch_bounds__(256)
void dwbn_kernel(const float* __restrict__ x,
                 const float* __restrict__ q_dw,  const float* __restrict__ q_gamma,
                 const float* __restrict__ q_beta, const float* __restrict__ q_mean,
                 const float* __restrict__ q_var,
                 const float* __restrict__ kv_dw, const float* __restrict__ kv_gamma,
                 const float* __restrict__ kv_beta, const float* __restrict__ kv_mean,
                 const float* __restrict__ kv_var)
{
    const int g  = blockIdx.x;
    const int b  = blockIdx.y;
    const int c0 = g * 8;
    const int tid = threadIdx.x;

    __shared__ float sx[8][34 * 34];
    __shared__ float wq_s[72], wk_s[72];
    __shared__ float bn_s[32];

    for (int idx = tid; idx < 8 * 1156; idx += 256) {
        int cc = idx / 1156, i = idx - cc * 1156;
        int r = i / 34, col = i - r * 34;
        int iy = r - 1, ix = col - 1;
        float v = 0.f;
        if (iy >= 0 && iy < 32 && ix >= 0 && ix < 32)
            v = x[((size_t)b * C_ + c0 + cc) * HW_ + iy * 32 + ix];
        sx[cc][i] = v;
    }
    if (tid < 72) { wq_s[tid] = q_dw[c0 * 9 + tid]; wk_s[tid] = kv_dw[c0 * 9 + tid]; }
    if (tid < 8) {
        int c = c0 + tid;
        float iq = q_gamma[c] * rsqrtf(q_var[c] + BN_EPS);
        bn_s[tid]      = iq;
        bn_s[8 + tid]  = q_beta[c] - q_mean[c] * iq;
        float ik = kv_gamma[c] * rsqrtf(kv_var[c] + BN_EPS);
        bn_s[16 + tid] = ik;
        bn_s[24 + tid] = kv_beta[c] - kv_mean[c] * ik;
    }
    __syncthreads();

    for (int p = tid; p < HW_; p += 256) {
        int oy = p >> 5, ox = p & 31;
        float o8[8];
#pragma unroll
        for (int cc = 0; cc < 8; ++cc) {
            const float* sp = &sx[cc][oy * 34 + ox];
            float s = 0.f;
#pragma unroll
            for (int r = 0; r < 3; ++r)
#pragma unroll
                for (int ss = 0; ss < 3; ++ss)
                    s += wq_s[cc * 9 + r * 3 + ss] * sp[r * 34 + ss];
            o8[cc] = to_tf32f(s * bn_s[cc] + bn_s[8 + cc]);
        }
        float4* dst = reinterpret_cast<float4*>(g_yq + ((size_t)b * HW_ + p) * C_ + c0);
        dst[0] = make_float4(o8[0], o8[1], o8[2], o8[3]);
        dst[1] = make_float4(o8[4], o8[5], o8[6], o8[7]);
    }

    if (tid < HWK_) {
        int oy = tid >> 4, ox = tid & 15;
        float o8[8];
#pragma unroll
        for (int cc = 0; cc < 8; ++cc) {
            const float* sp = &sx[cc][(2 * oy) * 34 + 2 * ox];
            float s = 0.f;
#pragma unroll
            for (int r = 0; r < 3; ++r)
#pragma unroll
                for (int ss = 0; ss < 3; ++ss)
                    s += wk_s[cc * 9 + r * 3 + ss] * sp[r * 34 + ss];
            o8[cc] = to_tf32f(s * bn_s[16 + cc] + bn_s[24 + cc]);
        }
        float4* dst = reinterpret_cast<float4*>(g_ykv + ((size_t)b * HWK_ + tid) * C_ + c0);
        dst[0] = make_float4(o8[0], o8[1], o8[2], o8[3]);
        dst[1] = make_float4(o8[4], o8[5], o8[6], o8[7]);
    }
}

// ---------------------------------------------------------------------------
// Kernel 2: tf32 GEMM, cp.async + ldmatrix, k-chunk 32 (12 chunks).
//   smem per buf/op: [128 rows][36 floats] (32 data + 4 pad). 144B row stride:
//   each ldmatrix 8-row phase covers banks {4r..4r+3}, r=0..7 -> conflict-free.
//   Dynamic smem 73728 B, double-buffered, 2 CTAs/SM.
// ---------------------------------------------------------------------------
#define G_PLANE 18432u             // 128 * 36 * 4 bytes
#define G_BUF   (2u * G_PLANE)     // A + B planes
#define G_SMEM  (2u * G_BUF)       // double buffer = 73728

template <int OUTMODE>
__global__ __launch_bounds__(256, 2)
void gemm_mma(const float* __restrict__ Amat, const float* __restrict__ Bmat,
              float* __restrict__ Cout, const float* __restrict__ bias, int Nt)
{
    extern __shared__ char gsm[];

    const int tid  = threadIdx.x;
    const int lane = tid & 31;
    const int w    = tid >> 5;
    const int mw   = w & 1;
    const int nw   = w >> 1;
    const int qrow = lane >> 2;
    const int q4   = lane & 3;

    int m0, n0;
    if (OUTMODE == 0) { n0 = blockIdx.x * 128; m0 = blockIdx.y * 128; }
    else              { m0 = blockIdx.x * 128; n0 = blockIdx.y * 128; }

    const uint32_t sbase = (uint32_t)__cvta_generic_to_shared(gsm);

    // cp.async mapping: seg = tid&7 (16B), row = tid>>3 (+32*i)
    const int cseg = tid & 7;
    const int crow = tid >> 3;
    const float* aptr = Amat + (size_t)(m0 + crow) * 384 + cseg * 4;
    const float* bptr = Bmat + (size_t)(n0 + crow) * 384 + cseg * 4;
    const uint32_t dstA = sbase + (uint32_t)(crow * 144 + cseg * 16);
    const uint32_t dstB = dstA + G_PLANE;

    float acc[4][4][4];
#pragma unroll
    for (int f = 0; f < 4; ++f)
#pragma unroll
        for (int j = 0; j < 4; ++j)
#pragma unroll
            for (int e = 0; e < 4; ++e) acc[f][j][e] = 0.f;

    // issue chunk 0
    {
#pragma unroll
        for (int i = 0; i < 4; ++i) {
            cp16(dstA + (uint32_t)(i * 32 * 144), aptr + (size_t)(i * 32) * 384);
            cp16(dstB + (uint32_t)(i * 32 * 144), bptr + (size_t)(i * 32) * 384);
        }
        asm volatile("cp.async.commit_group;");
    }

    int buf = 0;
    for (int c = 0; c < 12; ++c) {
        if (c + 1 < 12) {
            uint32_t bo = (uint32_t)(buf ^ 1) * G_BUF;
            const float* an = aptr + (c + 1) * 32;
            const float* bn = bptr + (c + 1) * 32;
#pragma unroll
            for (int i = 0; i < 4; ++i) {
                cp16(dstA + bo + (uint32_t)(i * 32 * 144), an + (size_t)(i * 32) * 384);
                cp16(dstB + bo + (uint32_t)(i * 32 * 144), bn + (size_t)(i * 32) * 384);
            }
            asm volatile("cp.async.commit_group;");
            asm volatile("cp.async.wait_group 1;");
        } else {
            asm volatile("cp.async.wait_group 0;");
        }
        __syncthreads();

        const uint32_t abase = sbase + (uint32_t)buf * G_BUF;
        const uint32_t bbase = abase + G_PLANE;
#pragma unroll
        for (int grp = 0; grp < 4; ++grp) {
            uint32_t a[4][4];
#pragma unroll
            for (int f = 0; f < 4; ++f) {
                uint32_t addr = abase
                    + (uint32_t)((mw * 64 + f * 16 + (lane & 15)) * 144)
                    + (uint32_t)(grp * 32 + (lane >> 4) * 16);
                ldsm_x4(a[f], addr);
            }
            uint32_t bf[4][2];
#pragma unroll
            for (int j = 0; j < 4; ++j) {
                uint32_t addr = bbase
                    + (uint32_t)((nw * 32 + j * 8 + (lane & 7)) * 144)
                    + (uint32_t)(grp * 32 + ((lane >> 3) & 1) * 16);
                ldsm_x2(bf[j], addr);
            }
#pragma unroll
            for (int f = 0; f < 4; ++f)
#pragma unroll
                for (int j = 0; j < 4; ++j)
                    mma_tf32(acc[f][j], a[f], bf[j]);
        }
        __syncthreads();
        buf ^= 1;
    }

#pragma unroll
    for (int f = 0; f < 4; ++f) {
#pragma unroll
        for (int j = 0; j < 4; ++j) {
            int gm = m0 + mw * 64 + f * 16 + qrow;
            int gn = n0 + nw * 32 + j * 8 + q4 * 2;
            if (OUTMODE == 0) {
                *reinterpret_cast<float2*>(&Cout[(size_t)gm * Nt + gn]) =
                    make_float2(to_tf32f(acc[f][j][0]), to_tf32f(acc[f][j][1]));
                *reinterpret_cast<float2*>(&Cout[(size_t)(gm + 8) * Nt + gn]) =
                    make_float2(to_tf32f(acc[f][j][2]), to_tf32f(acc[f][j][3]));
            } else {
                int bb  = gn >> 10;
                int pix = gn & 1023;
                float bv0 = bias[gm];
                float bv1 = bias[gm + 8];
                *reinterpret_cast<float2*>(
                    &Cout[((size_t)bb * C_ + gm) * HW_ + pix]) =
                    make_float2(acc[f][j][0] + bv0, acc[f][j][1] + bv0);
                *reinterpret_cast<float2*>(
                    &Cout[((size_t)bb * C_ + gm + 8) * HW_ + pix]) =
                    make_float2(acc[f][j][2] + bv1, acc[f][j][3] + bv1);
            }
        }
    }
}

// ---------------------------------------------------------------------------
// Kernel 3: attention, tensor-core, 256 threads / 128-query tiles,
// K/V staged PER PHASE (128 keys) -> smem 101376 B -> 2 CTAs/SM.
// Layouts:
//   Ks/Qs: [g 8 | stride 1032][row 128][8]  (pair (d,d+4) at 2*q4, 2*q4+1)
//   Vs:    [f 16 | stride 552][jw 8 | stride 68][d 64]
// ---------------------------------------------------------------------------
#define AKQ_G 1032
#define AV_F  552
#define AV_J  68
#define ATTN_SMEM_BYTES ((2 * 8 * AKQ_G + 16 * AV_F) * 4)   // 101376

__global__ __launch_bounds__(256, 2)
void attn_mma_kernel()
{
    extern __shared__ float sm[];
    float* Ks = sm;                  // 8 * 1032
    float* Qs = sm + 8 * AKQ_G;      // 8 * 1032
    float* Vs = Qs + 8 * AKQ_G;      // 16 * 552

    const int qt = blockIdx.x;   // 0..7
    const int h  = blockIdx.y;
    const int b  = blockIdx.z;
    const int tid  = threadIdx.x;
    const int w    = tid >> 5;   // 0..7
    const int lane = tid & 31;
    const int r  = lane >> 2;
    const int q4 = lane & 3;
    const int q0 = qt * 128;

    // ---- stage Q (128 queries, pre-scaled) ----
    for (int idx = tid; idx < 128 * 16; idx += 256) {
        int m = idx >> 4, f4 = idx & 15;
        float4 qq = reinterpret_cast<const float4*>(
            g_Q + ((size_t)(b * HW_ + q0 + m)) * INNER + h * DHEAD)[f4];
        int g = f4 >> 1, s = f4 & 1;
        float* qd = Qs + g * AKQ_G + m * 8 + s;
        qd[0] = qq.x * SCALE; qd[2] = qq.y * SCALE;
        qd[4] = qq.z * SCALE; qd[6] = qq.w * SCALE;
    }

    float dacc[8][4];
#pragma unroll
    for (int n = 0; n < 8; ++n)
#pragma unroll
        for (int e = 0; e < 4; ++e) dacc[n][e] = 0.f;

    float mrow0 = -1e30f, mrow1 = -1e30f, lrow0 = 0.f, lrow1 = 0.f;

#pragma unroll
    for (int ph = 0; ph < 2; ++ph) {
        if (ph) __syncthreads();   // all warps done reading previous K/V
        // ---- stage K, V for this phase's 128 keys ----
        for (int idx = tid; idx < 128 * 16; idx += 256) {
            int j = idx >> 4, f4 = idx & 15;
            const float4* kvp = reinterpret_cast<const float4*>(
                g_KV + ((size_t)(b * HWK_ + ph * 128 + j)) * (2 * INNER) + h * DHEAD);
            float4 kk = kvp[f4];
            float4 vv = kvp[96 + f4];
            int g = f4 >> 1, s = f4 & 1;
            float* kd = Ks + g * AKQ_G + j * 8 + s;
            kd[0] = kk.x; kd[2] = kk.y; kd[4] = kk.z; kd[6] = kk.w;
            *reinterpret_cast<float4*>(
                Vs + (j >> 3) * AV_F + (j & 7) * AV_J + (f4 << 2)) = vv;
        }
        __syncthreads();

        // ---- S = Q K^T over 128 keys ----
        float sacc[16][4];
#pragma unroll
        for (int f2 = 0; f2 < 16; ++f2)
#pragma unroll
            for (int e = 0; e < 4; ++e) sacc[f2][e] = 0.f;

#pragma unroll
        for (int g = 0; g < 8; ++g) {
            float2 alo = *reinterpret_cast<const float2*>(
                Qs + g * AKQ_G + ((w << 4) + r) * 8 + q4 * 2);
            float2 ahi = *reinterpret_cast<const float2*>(
                Qs + g * AKQ_G + ((w << 4) + 8 + r) * 8 + q4 * 2);
            uint32_t a[4] = { __float_as_uint(alo.x), __float_as_uint(ahi.x),
                              __float_as_uint(alo.y), __float_as_uint(ahi.y) };
#pragma unroll
            for (int f2 = 0; f2 < 16; ++f2) {
                float2 bb = *reinterpret_cast<const float2*>(
                    Ks + g * AKQ_G + ((f2 << 3) + r) * 8 + q4 * 2);
                uint32_t bf[2] = { __float_as_uint(bb.x), __float_as_uint(bb.y) };
                mma_tf32(sacc[f2], a, bf);
            }
        }

        // ---- softmax (rows r and r+8; quad shares a row) ----
        float ml0 = -1e30f, ml1 = -1e30f;
#pragma unroll
        for (int f2 = 0; f2 < 16; ++f2) {
            ml0 = fmaxf(ml0, fmaxf(sacc[f2][0], sacc[f2][1]));
            ml1 = fmaxf(ml1, fmaxf(sacc[f2][2], sacc[f2][3]));
        }
        ml0 = fmaxf(ml0, __shfl_xor_sync(0xffffffffu, ml0, 1));
        ml0 = fmaxf(ml0, __shfl_xor_sync(0xffffffffu, ml0, 2));
        ml1 = fmaxf(ml1, __shfl_xor_sync(0xffffffffu, ml1, 1));
        ml1 = fmaxf(ml1, __shfl_xor_sync(0xffffffffu, ml1, 2));

        float mn0 = (ph == 0) ? ml0 : fmaxf(mrow0, ml0);
        float mn1 = (ph == 0) ? ml1 : fmaxf(mrow1, ml1);
        float rs0 = (ph == 0) ? 0.f : __expf(mrow0 - mn0);
        float rs1 = (ph == 0) ? 0.f : __expf(mrow1 - mn1);

        float ls0 = 0.f, ls1 = 0.f;
#pragma unroll
        for (int f2 = 0; f2 < 16; ++f2) {
            float p0 = __expf(sacc[f2][0] - mn0); ls0 += p0; sacc[f2][0] = to_tf32f(p0);
            float p1 = __expf(sacc[f2][1] - mn0); ls0 += p1; sacc[f2][1] = to_tf32f(p1);
            float p2 = __expf(sacc[f2][2] - mn1); ls1 += p2; sacc[f2][2] = to_tf32f(p2);
            float p3 = __expf(sacc[f2][3] - mn1); ls1 += p3; sacc[f2][3] = to_tf32f(p3);
        }
        ls0 += __shfl_xor_sync(0xffffffffu, ls0, 1);
        ls0 += __shfl_xor_sync(0xffffffffu, ls0, 2);
        ls1 += __shfl_xor_sync(0xffffffffu, ls1, 1);
        ls1 += __shfl_xor_sync(0xffffffffu, ls1, 2);

        if (ph == 0) {
            lrow0 = ls0; lrow1 = ls1;
        } else {
            lrow0 = lrow0 * rs0 + ls0;
            lrow1 = lrow1 * rs1 + ls1;
#pragma unroll
            for (int n = 0; n < 8; ++n) {
                dacc[n][0] *= rs0; dacc[n][1] *= rs0;
                dacc[n][2] *= rs1; dacc[n][3] *= rs1;
            }
        }
        mrow0 = mn0; mrow1 = mn1;

        // ---- D += P V (A-fragments straight from sacc registers) ----
#pragma unroll
        for (int fg = 0; fg < 16; ++fg) {
            uint32_t a[4] = { __float_as_uint(sacc[fg][0]), __float_as_uint(sacc[fg][2]),
                              __float_as_uint(sacc[fg][1]), __float_as_uint(sacc[fg][3]) };
            const float* vb0 = Vs + fg * AV_F + (q4 * 2) * AV_J + r;
#pragma unroll
            for (int n = 0; n < 8; ++n) {
                uint32_t bf[2] = { __float_as_uint(vb0[(n << 3)]),
                                   __float_as_uint(vb0[(n << 3) + AV_J]) };
                mma_tf32(dacc[n], a, bf);
            }
        }
    }

    // ---- epilogue ----
    float li0 = 1.f / lrow0, li1 = 1.f / lrow1;
    const int row0 = b * HW_ + q0 + (w << 4) + r;
#pragma unroll
    for (int n = 0; n < 8; ++n) {
        *reinterpret_cast<float2*>(
            g_O + (size_t)row0 * INNER + h * DHEAD + (n << 3) + q4 * 2) =
            make_float2(to_tf32f(dacc[n][0] * li0), to_tf32f(dacc[n][1] * li0));
        *reinterpret_cast<float2*>(
            g_O + (size_t)(row0 + 8) * INNER + h * DHEAD + (n << 3) + q4 * 2) =
            make_float2(to_tf32f(dacc[n][2] * li1), to_tf32f(dacc[n][3] * li1));
    }
}

// ---------------------------------------------------------------------------
// launcher
// ---------------------------------------------------------------------------
extern "C" void kernel_launch(void* const* d_in, const int* in_sizes, int n_in,
                              void* d_out, int out_size)
{
    (void)in_sizes; (void)n_in; (void)out_size;

    const float* x        = (const float*)d_in[0];
    const float* q_dw     = (const float*)d_in[1];
    const float* q_gamma  = (const float*)d_in[2];
    const float* q_beta   = (const float*)d_in[3];
    const float* q_mean   = (const float*)d_in[4];
    const float* q_var    = (const float*)d_in[5];
    const float* q_pw     = (const float*)d_in[6];
    const float* kv_dw    = (const float*)d_in[7];
    const float* kv_gamma = (const float*)d_in[8];
    const float* kv_beta  = (const float*)d_in[9];
    const float* kv_mean  = (const float*)d_in[10];
    const float* kv_var   = (const float*)d_in[11];
    const float* kv_pw    = (const float*)d_in[12];
    const float* out_w    = (const float*)d_in[13];
    const float* out_b    = (const float*)d_in[14];
    float* out = (float*)d_out;

    void *p_yq, *p_ykv, *p_Q, *p_KV, *p_O, *p_w;
    cudaGetSymbolAddress(&p_yq,  g_yq);
    cudaGetSymbolAddress(&p_ykv, g_ykv);
    cudaGetSymbolAddress(&p_Q,   g_Q);
    cudaGetSymbolAddress(&p_KV,  g_KV);
    cudaGetSymbolAddress(&p_O,   g_O);
    cudaGetSymbolAddress(&p_w,   g_w);
    const float* wbuf = (const float*)p_w;

    // raise dynamic smem limits
    cudaFuncSetAttribute(gemm_mma<0>,
                         cudaFuncAttributeMaxDynamicSharedMemorySize, G_SMEM);
    cudaFuncSetAttribute(gemm_mma<1>,
                         cudaFuncAttributeMaxDynamicSharedMemorySize, G_SMEM);
    cudaFuncSetAttribute(attn_mma_kernel,
                         cudaFuncAttributeMaxDynamicSharedMemorySize,
                         ATTN_SMEM_BYTES);

    // 0) pre-round weights
    prep_weights<<<(WO_OFF + C_ * INNER + 255) / 256, 256>>>(q_pw, kv_pw, out_w);

    // 1) depthwise conv + BN, transposed tf32-rounded activations
    dwbn_kernel<<<dim3(C_ / 8, B_), 256>>>(x,
        q_dw, q_gamma, q_beta, q_mean, q_var,
        kv_dw, kv_gamma, kv_beta, kv_mean, kv_var);

    // 2) Q pointwise: m=pix (32768), n=ch (384) -> row-major g_Q
    gemm_mma<0><<<dim3(INNER / 128, (B_ * HW_) / 128), 256, G_SMEM>>>(
        (const float*)p_yq, wbuf + WQ_OFF, (float*)p_Q, nullptr, INNER);

    // 3) KV pointwise: m=pix (8192), n=ch (768) -> row-major g_KV
    gemm_mma<0><<<dim3((2 * INNER) / 128, (B_ * HWK_) / 128), 256, G_SMEM>>>(
        (const float*)p_ykv, wbuf + WKV_OFF, (float*)p_KV, nullptr, 2 * INNER);

    // 4) attention (tensor-core, 2 CTAs/SM)
    attn_mma_kernel<<<dim3(8, HEADS, B_), 256, ATTN_SMEM_BYTES>>>();

    // 5) output projection: m=ch (384), n=pix (32768) -> NCHW + bias
    gemm_mma<1><<<dim3(C_ / 128, (B_ * HW_) / 128), 256, G_SMEM>>>(
        wbuf + WO_OFF, (const float*)p_O, out, out_b, 0);
}

// round 17
// speedup vs baseline: 1.3453x; 1.3453x over previous
#include <cuda_runtime.h>
#include <cuda_bf16.h>
#include <cstdint>
#include <cstddef>

// Problem constants
#define B_    32
#define C_    384
#define H_    32
#define W_    32
#define HW_   1024
#define HK_   16
#define WK_   16
#define HWK_  256
#define HEADS 6
#define DHEAD 64
#define INNER 384          // HEADS*DHEAD
#define SCALE 0.125f       // DIM_HEAD^-0.5
#define BN_EPS 1e-5f

typedef unsigned long long u64;

// ---------------------------------------------------------------------------
// tf32 helpers
// ---------------------------------------------------------------------------
__device__ __forceinline__ float to_tf32f(float x) {
    uint32_t r; asm("cvt.rna.tf32.f32 %0, %1;" : "=r"(r) : "f"(x));
    return __uint_as_float(r);
}
__device__ __forceinline__ void mma_tf32(float* d, const uint32_t* a, const uint32_t* b) {
    asm volatile(
        "mma.sync.aligned.m16n8k8.row.col.f32.tf32.tf32.f32 "
        "{%0,%1,%2,%3}, {%4,%5,%6,%7}, {%8,%9}, {%0,%1,%2,%3};"
        : "+f"(d[0]), "+f"(d[1]), "+f"(d[2]), "+f"(d[3])
        : "r"(a[0]), "r"(a[1]), "r"(a[2]), "r"(a[3]), "r"(b[0]), "r"(b[1]));
}
__device__ __forceinline__ void ldsm_x4(uint32_t* r, uint32_t addr) {
    asm volatile("ldmatrix.sync.aligned.m8n8.x4.shared.b16 {%0,%1,%2,%3}, [%4];"
        : "=r"(r[0]), "=r"(r[1]), "=r"(r[2]), "=r"(r[3]) : "r"(addr));
}
__device__ __forceinline__ void ldsm_x2(uint32_t* r, uint32_t addr) {
    asm volatile("ldmatrix.sync.aligned.m8n8.x2.shared.b16 {%0,%1}, [%2];"
        : "=r"(r[0]), "=r"(r[1]) : "r"(addr));
}
__device__ __forceinline__ void cp16(uint32_t dst, const void* src) {
    asm volatile("cp.async.ca.shared.global [%0], [%1], 16;" :: "r"(dst), "l"(src));
}

// ---------------------------------------------------------------------------
// Scratch (static device globals; no runtime allocation allowed)
// ---------------------------------------------------------------------------
__device__ float g_yq [(size_t)B_ * HW_ * C_];          // dw+bn out, Q path (tf32-rounded)
__device__ float g_ykv[(size_t)B_ * HWK_ * C_];         // dw+bn out, KV path (tf32-rounded)
__device__ float g_Q  [(size_t)B_ * HW_ * INNER];       // Q row-major (tf32-rounded)
__device__ float g_KV [(size_t)B_ * HWK_ * 2 * INNER];  // KV row-major (tf32-rounded)
__device__ float g_O  [(size_t)B_ * HW_ * INNER];       // attention out (tf32-rounded)

#define WQ_OFF  0
#define WKV_OFF (INNER * C_)                             // 147456
#define WO_OFF  (WQ_OFF + INNER * C_ + 2 * INNER * C_)   // 442368
__device__ float g_w[INNER * C_ + 2 * INNER * C_ + C_ * INNER];

// ---------------------------------------------------------------------------
// Kernel 0: pre-round weights to tf32 (rna)
// ---------------------------------------------------------------------------
__global__ __launch_bounds__(256)
void prep_weights(const float* __restrict__ q_pw, const float* __restrict__ kv_pw,
                  const float* __restrict__ out_w)
{
    int i = blockIdx.x * 256 + threadIdx.x;
    if (i < WKV_OFF)          g_w[i] = to_tf32f(q_pw[i]);
    else if (i < WO_OFF)      g_w[i] = to_tf32f(kv_pw[i - WKV_OFF]);
    else if (i < WO_OFF + C_ * INNER) g_w[i] = to_tf32f(out_w[i - WO_OFF]);
}

// ---------------------------------------------------------------------------
// Kernel 1: fused depthwise 3x3 (+BN), 8-channel groups, transposed tf32 out
// ---------------------------------------------------------------------------
__global__ __launch_bounds__(256)
void dwbn_kernel(const float* __restrict__ x,
                 const float* __restrict__ q_dw,  const float* __restrict__ q_gamma,
                 const float* __restrict__ q_beta, const float* __restrict__ q_mean,
                 const float* __restrict__ q_var,
                 const float* __restrict__ kv_dw, const float* __restrict__ kv_gamma,
                 const float* __restrict__ kv_beta, const float* __restrict__ kv_mean,
                 const float* __restrict__ kv_var)
{
    const int g  = blockIdx.x;
    const int b  = blockIdx.y;
    const int c0 = g * 8;
    const int tid = threadIdx.x;

    __shared__ float sx[8][34 * 34];
    __shared__ float wq_s[72], wk_s[72];
    __shared__ float bn_s[32];

    for (int idx = tid; idx < 8 * 1156; idx += 256) {
        int cc = idx / 1156, i = idx - cc * 1156;
        int r = i / 34, col = i - r * 34;
        int iy = r - 1, ix = col - 1;
        float v = 0.f;
        if (iy >= 0 && iy < 32 && ix >= 0 && ix < 32)
            v = x[((size_t)b * C_ + c0 + cc) * HW_ + iy * 32 + ix];
        sx[cc][i] = v;
    }
    if (tid < 72) { wq_s[tid] = q_dw[c0 * 9 + tid]; wk_s[tid] = kv_dw[c0 * 9 + tid]; }
    if (tid < 8) {
        int c = c0 + tid;
        float iq = q_gamma[c] * rsqrtf(q_var[c] + BN_EPS);
        bn_s[tid]      = iq;
        bn_s[8 + tid]  = q_beta[c] - q_mean[c] * iq;
        float ik = kv_gamma[c] * rsqrtf(kv_var[c] + BN_EPS);
        bn_s[16 + tid] = ik;
        bn_s[24 + tid] = kv_beta[c] - kv_mean[c] * ik;
    }
    __syncthreads();

    for (int p = tid; p < HW_; p += 256) {
        int oy = p >> 5, ox = p & 31;
        float o8[8];
#pragma unroll
        for (int cc = 0; cc < 8; ++cc) {
            const float* sp = &sx[cc][oy * 34 + ox];
            float s = 0.f;
#pragma unroll
            for (int r = 0; r < 3; ++r)
#pragma unroll
                for (int ss = 0; ss < 3; ++ss)
                    s += wq_s[cc * 9 + r * 3 + ss] * sp[r * 34 + ss];
            o8[cc] = to_tf32f(s * bn_s[cc] + bn_s[8 + cc]);
        }
        float4* dst = reinterpret_cast<float4*>(g_yq + ((size_t)b * HW_ + p) * C_ + c0);
        dst[0] = make_float4(o8[0], o8[1], o8[2], o8[3]);
        dst[1] = make_float4(o8[4], o8[5], o8[6], o8[7]);
    }

    if (tid < HWK_) {
        int oy = tid >> 4, ox = tid & 15;
        float o8[8];
#pragma unroll
        for (int cc = 0; cc < 8; ++cc) {
            const float* sp = &sx[cc][(2 * oy) * 34 + 2 * ox];
            float s = 0.f;
#pragma unroll
            for (int r = 0; r < 3; ++r)
#pragma unroll
                for (int ss = 0; ss < 3; ++ss)
                    s += wk_s[cc * 9 + r * 3 + ss] * sp[r * 34 + ss];
            o8[cc] = to_tf32f(s * bn_s[16 + cc] + bn_s[24 + cc]);
        }
        float4* dst = reinterpret_cast<float4*>(g_ykv + ((size_t)b * HWK_ + tid) * C_ + c0);
        dst[0] = make_float4(o8[0], o8[1], o8[2], o8[3]);
        dst[1] = make_float4(o8[4], o8[5], o8[6], o8[7]);
    }
}

// ---------------------------------------------------------------------------
// Kernel 2: tf32 GEMM, cp.async + ldmatrix, k-chunk 16, THREE buffers,
// single __syncthreads per chunk (wait -> sync -> issue(c+2) -> compute(c)).
//   smem per buf/op: [128 rows][20 floats] (16 data + 4 pad, 80B row stride).
//   Dynamic smem 61440 B, 2 CTAs/SM.
// ---------------------------------------------------------------------------
#define GP_PLANE 10240u            // 128 * 20 * 4 bytes
#define GP_BUF   (2u * GP_PLANE)   // A + B planes = 20480
#define GP_SMEM  (3u * GP_BUF)     // 61440

template <int OUTMODE>
__global__ __launch_bounds__(256, 2)
void gemm_mma(const float* __restrict__ Amat, const float* __restrict__ Bmat,
              float* __restrict__ Cout, const float* __restrict__ bias, int Nt)
{
    extern __shared__ char gsm[];

    const int tid  = threadIdx.x;
    const int lane = tid & 31;
    const int w    = tid >> 5;
    const int mw   = w & 1;
    const int nw   = w >> 1;
    const int qrow = lane >> 2;
    const int q4   = lane & 3;

    int m0, n0;
    if (OUTMODE == 0) { n0 = blockIdx.x * 128; m0 = blockIdx.y * 128; }
    else              { m0 = blockIdx.x * 128; n0 = blockIdx.y * 128; }

    const uint32_t sbase = (uint32_t)__cvta_generic_to_shared(gsm);

    // cp.async mapping: seg = tid&3 (16B), rows tid>>2 and tid>>2 + 64
    const int cseg = tid & 3;
    const int crow = tid >> 2;
    const float* aptr = Amat + (size_t)(m0 + crow) * 384 + cseg * 4;
    const float* bptr = Bmat + (size_t)(n0 + crow) * 384 + cseg * 4;
    const uint32_t dstA = sbase + (uint32_t)(crow * 80 + cseg * 16);
    const uint32_t dstB = dstA + GP_PLANE;

    float acc[4][4][4];
#pragma unroll
    for (int f = 0; f < 4; ++f)
#pragma unroll
        for (int j = 0; j < 4; ++j)
#pragma unroll
            for (int e = 0; e < 4; ++e) acc[f][j][e] = 0.f;

    // prologue: issue chunks 0 and 1
#pragma unroll
    for (int c = 0; c < 2; ++c) {
        uint32_t bo = (uint32_t)c * GP_BUF;
        cp16(dstA + bo,           aptr + c * 16);
        cp16(dstA + bo + 64 * 80, aptr + c * 16 + (size_t)64 * 384);
        cp16(dstB + bo,           bptr + c * 16);
        cp16(dstB + bo + 64 * 80, bptr + c * 16 + (size_t)64 * 384);
        asm volatile("cp.async.commit_group;");
    }

    int buf = 0;   // chunk c lives in buffer c % 3
    for (int c = 0; c < 24; ++c) {
        if (c + 1 < 24) asm volatile("cp.async.wait_group 1;");
        else            asm volatile("cp.async.wait_group 0;");
        __syncthreads();   // chunk c visible; all warps past compute of c-1

        if (c + 2 < 24) {  // refill buffer (c+2)%3 (= (c-1)%3, safe after sync)
            int nb = buf + 2; if (nb >= 3) nb -= 3;
            uint32_t bo = (uint32_t)nb * GP_BUF;
            const float* an = aptr + (c + 2) * 16;
            const float* bn = bptr + (c + 2) * 16;
            cp16(dstA + bo,           an);
            cp16(dstA + bo + 64 * 80, an + (size_t)64 * 384);
            cp16(dstB + bo,           bn);
            cp16(dstB + bo + 64 * 80, bn + (size_t)64 * 384);
            asm volatile("cp.async.commit_group;");
        }

        const uint32_t abase = sbase + (uint32_t)buf * GP_BUF;
        const uint32_t bbase = abase + GP_PLANE;
#pragma unroll
        for (int grp = 0; grp < 2; ++grp) {
            uint32_t a[4][4];
#pragma unroll
            for (int f = 0; f < 4; ++f) {
                uint32_t addr = abase
                    + (uint32_t)((mw * 64 + f * 16 + (lane & 15)) * 80)
                    + (uint32_t)(grp * 32 + (lane >> 4) * 16);
                ldsm_x4(a[f], addr);
            }
            uint32_t bf[4][2];
#pragma unroll
            for (int j = 0; j < 4; ++j) {
                uint32_t addr = bbase
                    + (uint32_t)((nw * 32 + j * 8 + (lane & 7)) * 80)
                    + (uint32_t)(grp * 32 + ((lane >> 3) & 1) * 16);
                ldsm_x2(bf[j], addr);
            }
#pragma unroll
            for (int f = 0; f < 4; ++f)
#pragma unroll
                for (int j = 0; j < 4; ++j)
                    mma_tf32(acc[f][j], a[f], bf[j]);
        }
        if (++buf == 3) buf = 0;
    }

#pragma unroll
    for (int f = 0; f < 4; ++f) {
#pragma unroll
        for (int j = 0; j < 4; ++j) {
            int gm = m0 + mw * 64 + f * 16 + qrow;
            int gn = n0 + nw * 32 + j * 8 + q4 * 2;
            if (OUTMODE == 0) {
                *reinterpret_cast<float2*>(&Cout[(size_t)gm * Nt + gn]) =
                    make_float2(to_tf32f(acc[f][j][0]), to_tf32f(acc[f][j][1]));
                *reinterpret_cast<float2*>(&Cout[(size_t)(gm + 8) * Nt + gn]) =
                    make_float2(to_tf32f(acc[f][j][2]), to_tf32f(acc[f][j][3]));
            } else {
                int bb  = gn >> 10;
                int pix = gn & 1023;
                float bv0 = bias[gm];
                float bv1 = bias[gm + 8];
                *reinterpret_cast<float2*>(
                    &Cout[((size_t)bb * C_ + gm) * HW_ + pix]) =
                    make_float2(acc[f][j][0] + bv0, acc[f][j][1] + bv0);
                *reinterpret_cast<float2*>(
                    &Cout[((size_t)bb * C_ + gm + 8) * HW_ + pix]) =
                    make_float2(acc[f][j][2] + bv1, acc[f][j][3] + bv1);
            }
        }
    }
}

// ---------------------------------------------------------------------------
// Kernel 3: attention, full tensor-core, 512 threads / 256-query tiles
// (verbatim round-14: best measured config).
//   Ks/Qs: [g 8 | stride 2056][row 256][8]; Vs: [f 32 | 552][jw 8 | 68][d 64]
// ---------------------------------------------------------------------------
#define KQ_G_STRIDE 2056
#define V_F_STRIDE  552
#define V_J_STRIDE  68
#define ATTN_SMEM_BYTES ((2 * 8 * KQ_G_STRIDE + 32 * V_F_STRIDE) * 4)

__global__ __launch_bounds__(512)
void attn_mma_kernel()
{
    extern __shared__ float sm[];
    float* Ks = sm;                            // 8 * 2056
    float* Qs = sm + 8 * KQ_G_STRIDE;          // 8 * 2056
    float* Vs = Qs + 8 * KQ_G_STRIDE;          // 32 * 552

    const int qt = blockIdx.x;   // 0..3
    const int h  = blockIdx.y;
    const int b  = blockIdx.z;
    const int tid  = threadIdx.x;
    const int w    = tid >> 5;   // 0..15
    const int lane = tid & 31;
    const int r  = lane >> 2;
    const int q4 = lane & 3;
    const int q0 = qt * 256;

    for (int idx = tid; idx < 256 * 16; idx += 512) {
        int j = idx >> 4, f4 = idx & 15;
        const float4* kvp = reinterpret_cast<const float4*>(
            g_KV + ((size_t)(b * HWK_ + j)) * (2 * INNER) + h * DHEAD);
        float4 kk = kvp[f4];
        float4 vv = kvp[96 + f4];
        int g = f4 >> 1, s = f4 & 1;
        float* kd = Ks + g * KQ_G_STRIDE + j * 8 + s;
        kd[0] = kk.x; kd[2] = kk.y; kd[4] = kk.z; kd[6] = kk.w;
        *reinterpret_cast<float4*>(
            Vs + (j >> 3) * V_F_STRIDE + (j & 7) * V_J_STRIDE + (f4 << 2)) = vv;
    }
    for (int idx = tid; idx < 256 * 16; idx += 512) {
        int m = idx >> 4, f4 = idx & 15;
        float4 qq = reinterpret_cast<const float4*>(
            g_Q + ((size_t)(b * HW_ + q0 + m)) * INNER + h * DHEAD)[f4];
        int g = f4 >> 1, s = f4 & 1;
        float* qd = Qs + g * KQ_G_STRIDE + m * 8 + s;
        qd[0] = qq.x * SCALE; qd[2] = qq.y * SCALE;
        qd[4] = qq.z * SCALE; qd[6] = qq.w * SCALE;
    }
    __syncthreads();

    float dacc[8][4];
#pragma unroll
    for (int n = 0; n < 8; ++n)
#pragma unroll
        for (int e = 0; e < 4; ++e) dacc[n][e] = 0.f;

    float mrow0 = -1e30f, mrow1 = -1e30f, lrow0 = 0.f, lrow1 = 0.f;

#pragma unroll
    for (int ph = 0; ph < 2; ++ph) {
        float sacc[16][4];
#pragma unroll
        for (int f2 = 0; f2 < 16; ++f2)
#pragma unroll
            for (int e = 0; e < 4; ++e) sacc[f2][e] = 0.f;

#pragma unroll
        for (int g = 0; g < 8; ++g) {
            float2 alo = *reinterpret_cast<const float2*>(
                Qs + g * KQ_G_STRIDE + ((w << 4) + r) * 8 + q4 * 2);
            float2 ahi = *reinterpret_cast<const float2*>(
                Qs + g * KQ_G_STRIDE + ((w << 4) + 8 + r) * 8 + q4 * 2);
            uint32_t a[4] = { __float_as_uint(alo.x), __float_as_uint(ahi.x),
                              __float_as_uint(alo.y), __float_as_uint(ahi.y) };
#pragma unroll
            for (int f2 = 0; f2 < 16; ++f2) {
                float2 bb = *reinterpret_cast<const float2*>(
                    Ks + g * KQ_G_STRIDE + ((ph << 7) + (f2 << 3) + r) * 8 + q4 * 2);
                uint32_t bf[2] = { __float_as_uint(bb.x), __float_as_uint(bb.y) };
                mma_tf32(sacc[f2], a, bf);
            }
        }

        float ml0 = -1e30f, ml1 = -1e30f;
#pragma unroll
        for (int f2 = 0; f2 < 16; ++f2) {
            ml0 = fmaxf(ml0, fmaxf(sacc[f2][0], sacc[f2][1]));
            ml1 = fmaxf(ml1, fmaxf(sacc[f2][2], sacc[f2][3]));
        }
        ml0 = fmaxf(ml0, __shfl_xor_sync(0xffffffffu, ml0, 1));
        ml0 = fmaxf(ml0, __shfl_xor_sync(0xffffffffu, ml0, 2));
        ml1 = fmaxf(ml1, __shfl_xor_sync(0xffffffffu, ml1, 1));
        ml1 = fmaxf(ml1, __shfl_xor_sync(0xffffffffu, ml1, 2));

        float mn0 = (ph == 0) ? ml0 : fmaxf(mrow0, ml0);
        float mn1 = (ph == 0) ? ml1 : fmaxf(mrow1, ml1);
        float rs0 = (ph == 0) ? 0.f : __expf(mrow0 - mn0);
        float rs1 = (ph == 0) ? 0.f : __expf(mrow1 - mn1);

        float ls0 = 0.f, ls1 = 0.f;
#pragma unroll
        for (int f2 = 0; f2 < 16; ++f2) {
            float p0 = __expf(sacc[f2][0] - mn0); ls0 += p0; sacc[f2][0] = to_tf32f(p0);
            float p1 = __expf(sacc[f2][1] - mn0); ls0 += p1; sacc[f2][1] = to_tf32f(p1);
            float p2 = __expf(sacc[f2][2] - mn1); ls1 += p2; sacc[f2][2] = to_tf32f(p2);
            float p3 = __expf(sacc[f2][3] - mn1); ls1 += p3; sacc[f2][3] = to_tf32f(p3);
        }
        ls0 += __shfl_xor_sync(0xffffffffu, ls0, 1);
        ls0 += __shfl_xor_sync(0xffffffffu, ls0, 2);
        ls1 += __shfl_xor_sync(0xffffffffu, ls1, 1);
        ls1 += __shfl_xor_sync(0xffffffffu, ls1, 2);

        if (ph == 0) {
            lrow0 = ls0; lrow1 = ls1;
        } else {
            lrow0 = lrow0 * rs0 + ls0;
            lrow1 = lrow1 * rs1 + ls1;
#pragma unroll
            for (int n = 0; n < 8; ++n) {
                dacc[n][0] *= rs0; dacc[n][1] *= rs0;
                dacc[n][2] *= rs1; dacc[n][3] *= rs1;
            }
        }
        mrow0 = mn0; mrow1 = mn1;

#pragma unroll
        for (int fg = 0; fg < 16; ++fg) {
            uint32_t a[4] = { __float_as_uint(sacc[fg][0]), __float_as_uint(sacc[fg][2]),
                              __float_as_uint(sacc[fg][1]), __float_as_uint(sacc[fg][3]) };
            int f = (ph << 4) + fg;
            const float* vb0 = Vs + f * V_F_STRIDE + (q4 * 2) * V_J_STRIDE + r;
#pragma unroll
            for (int n = 0; n < 8; ++n) {
                uint32_t bf[2] = { __float_as_uint(vb0[(n << 3)]),
                                   __float_as_uint(vb0[(n << 3) + V_J_STRIDE]) };
                mma_tf32(dacc[n], a, bf);
            }
        }
    }

    float li0 = 1.f / lrow0, li1 = 1.f / lrow1;
    const int row0 = b * HW_ + q0 + (w << 4) + r;
#pragma unroll
    for (int n = 0; n < 8; ++n) {
        *reinterpret_cast<float2*>(
            g_O + (size_t)row0 * INNER + h * DHEAD + (n << 3) + q4 * 2) =
            make_float2(to_tf32f(dacc[n][0] * li0), to_tf32f(dacc[n][1] * li0));
        *reinterpret_cast<float2*>(
            g_O + (size_t)(row0 + 8) * INNER + h * DHEAD + (n << 3) + q4 * 2) =
            make_float2(to_tf32f(dacc[n][2] * li1), to_tf32f(dacc[n][3] * li1));
    }
}

// ---------------------------------------------------------------------------
// launcher
// ---------------------------------------------------------------------------
extern "C" void kernel_launch(void* const* d_in, const int* in_sizes, int n_in,
                              void* d_out, int out_size)
{
    (void)in_sizes; (void)n_in; (void)out_size;

    const float* x        = (const float*)d_in[0];
    const float* q_dw     = (const float*)d_in[1];
    const float* q_gamma  = (const float*)d_in[2];
    const float* q_beta   = (const float*)d_in[3];
    const float* q_mean   = (const float*)d_in[4];
    const float* q_var    = (const float*)d_in[5];
    const float* q_pw     = (const float*)d_in[6];
    const float* kv_dw    = (const float*)d_in[7];
    const float* kv_gamma = (const float*)d_in[8];
    const float* kv_beta  = (const float*)d_in[9];
    const float* kv_mean  = (const float*)d_in[10];
    const float* kv_var   = (const float*)d_in[11];
    const float* kv_pw    = (const float*)d_in[12];
    const float* out_w    = (const float*)d_in[13];
    const float* out_b    = (const float*)d_in[14];
    float* out = (float*)d_out;

    void *p_yq, *p_ykv, *p_Q, *p_KV, *p_O, *p_w;
    cudaGetSymbolAddress(&p_yq,  g_yq);
    cudaGetSymbolAddress(&p_ykv, g_ykv);
    cudaGetSymbolAddress(&p_Q,   g_Q);
    cudaGetSymbolAddress(&p_KV,  g_KV);
    cudaGetSymbolAddress(&p_O,   g_O);
    cudaGetSymbolAddress(&p_w,   g_w);
    const float* wbuf = (const float*)p_w;

    // raise dynamic smem limits
    cudaFuncSetAttribute(gemm_mma<0>,
                         cudaFuncAttributeMaxDynamicSharedMemorySize, GP_SMEM);
    cudaFuncSetAttribute(gemm_mma<1>,
                         cudaFuncAttributeMaxDynamicSharedMemorySize, GP_SMEM);
    cudaFuncSetAttribute(attn_mma_kernel,
                         cudaFuncAttributeMaxDynamicSharedMemorySize,
                         ATTN_SMEM_BYTES);

    // 0) pre-round weights
    prep_weights<<<(WO_OFF + C_ * INNER + 255) / 256, 256>>>(q_pw, kv_pw, out_w);

    // 1) depthwise conv + BN, transposed tf32-rounded activations
    dwbn_kernel<<<dim3(C_ / 8, B_), 256>>>(x,
        q_dw, q_gamma, q_beta, q_mean, q_var,
        kv_dw, kv_gamma, kv_beta, kv_mean, kv_var);

    // 2) Q pointwise: m=pix (32768), n=ch (384) -> row-major g_Q
    gemm_mma<0><<<dim3(INNER / 128, (B_ * HW_) / 128), 256, GP_SMEM>>>(
        (const float*)p_yq, wbuf + WQ_OFF, (float*)p_Q, nullptr, INNER);

    // 3) KV pointwise: m=pix (8192), n=ch (768) -> row-major g_KV
    gemm_mma<0><<<dim3((2 * INNER) / 128, (B_ * HWK_) / 128), 256, GP_SMEM>>>(
        (const float*)p_ykv, wbuf + WKV_OFF, (float*)p_KV, nullptr, 2 * INNER);

    // 4) attention (full tensor-core, 512 threads, round-14 config)
    attn_mma_kernel<<<dim3(4, HEADS, B_), 512, ATTN_SMEM_BYTES>>>();

    // 5) output projection: m=ch (384), n=pix (32768) -> NCHW + bias
    gemm_mma<1><<<dim3(C_ / 128, (B_ * HW_) / 128), 256, GP_SMEM>>>(
        wbuf + WO_OFF, (const float*)p_O, out, out_b, 0);
}